// round 9
// baseline (speedup 1.0000x reference)
#include <cuda_runtime.h>
#include <cstdint>
#include <cstddef>

#define NB 4096
#define NT 512

// z trajectory scratch, layout (B, T, 4)
__device__ float g_z[(size_t)NB * NT * 4];

using ull = unsigned long long;

__device__ __forceinline__ ull pack2(float lo, float hi) {
    ull r; asm("mov.b64 %0, {%1, %2};" : "=l"(r) : "f"(lo), "f"(hi)); return r;
}
__device__ __forceinline__ float2 unpack2(ull v) {
    float2 r; asm("mov.b64 {%0, %1}, %2;" : "=f"(r.x), "=f"(r.y) : "l"(v)); return r;
}
// packed f32x2 FMA / ADD — PTX-only on sm_10x
__device__ __forceinline__ ull fma2(ull a, ull b, ull c) {
    ull d; asm("fma.rn.f32x2 %0, %1, %2, %3;" : "=l"(d) : "l"(a), "l"(b), "l"(c)); return d;
}
__device__ __forceinline__ ull add2(ull a, ull b) {
    ull d; asm("add.rn.f32x2 %0, %1, %2;" : "=l"(d) : "l"(a), "l"(b)); return d;
}
__device__ __forceinline__ ull shflx2(ull v, int d, int w) {
    float2 f = unpack2(v);
    f.x = __shfl_xor_sync(0xffffffffu, f.x, d, w);
    f.y = __shfl_xor_sync(0xffffffffu, f.y, d, w);
    return pack2(f.x, f.y);
}

// single-MUFU tanh (sm_75+). ~1e-4 accuracy, 16 cyc — shortens the
// loop-carried RNN chain vs exp-based tanh (~45 cyc).
__device__ __forceinline__ float tanh_approx(float x) {
    float r; asm("tanh.approx.f32 %0, %1;" : "=f"(r) : "f"(x)); return r;
}
__device__ __forceinline__ float eluf(float x) {
    return x > 0.0f ? x : (__expf(x) - 1.0f);
}

// ---------------------------------------------------------------------------
// Phase 1: reverse RNN scan + h2o + z0.  Octet layout, 128-thread blocks
// (4 warps -> all 4 SMSPs; 64-thread blocks leave SMSP 2,3 idle since
// SMSP = warp_id % 4).  lane = (s = lane>>3 -> batch, o = lane&7 -> units).
// Thread o owns hidden units {o, o+8, o+16} and (o==0) unit 24. Hidden state
// in registers, gathered per step with width-8 shuffles. No smem, no barriers.
// Grid 256 x 128 -> 1024 warps.
// ---------------------------------------------------------------------------
__global__ void __launch_bounds__(128) rnn_kernel(
    const float* __restrict__ trajs,
    const float* __restrict__ eps,
    const float* __restrict__ i2h_w,
    const float* __restrict__ i2h_b,
    const float* __restrict__ h2o_w,
    const float* __restrict__ h2o_b,
    float* __restrict__ out)
{
    const int lane = threadIdx.x & 31;
    const int wrp  = threadIdx.x >> 5;
    const int o    = lane & 7;
    const int s    = lane >> 3;
    const int b    = blockIdx.x * 16 + wrp * 4 + s;

    // per-thread weight slots (zero-masked invalid slots -> uniform flow)
    float wx0[4], wx1[4], wb[4], wh24[4];
    ull   whp[4][12];
    #pragma unroll
    for (int i = 0; i < 4; i++) {
        const bool v = (i < 3) || (o == 0);
        const int  j = v ? (o + 8 * i) : 0;
        const float sc = v ? 1.0f : 0.0f;
        wx0[i] = sc * i2h_w[0 * 25 + j];
        wx1[i] = sc * i2h_w[1 * 25 + j];
        wb[i]  = sc * i2h_b[j];
        #pragma unroll
        for (int p = 0; p < 12; p++)
            whp[i][p] = pack2(sc * i2h_w[(2 + 2 * p) * 25 + j],
                              sc * i2h_w[(3 + 2 * p) * 25 + j]);
        wh24[i] = sc * i2h_w[26 * 25 + j];
    }

    float hown[4] = {0.f, 0.f, 0.f, 0.f};
    const float* tb = trajs + (size_t)b * (NT * 2);
    float2 xv = *(const float2*)(tb + (NT - 1) * 2);   // prefetch

    for (int t = NT - 1; t >= 0; t--) {
        const float2 xcur = xv;
        if (t > 0) xv = *(const float2*)(tb + (t - 1) * 2);  // overlap next load

        // gather full h[25] of this batch from octet registers
        ull gp[12];
        #pragma unroll
        for (int p = 0; p < 12; p++) {
            const int j0 = 2 * p, j1 = 2 * p + 1;
            float a = __shfl_sync(0xffffffffu, hown[j0 >> 3], j0 & 7, 8);
            float c = __shfl_sync(0xffffffffu, hown[j1 >> 3], j1 & 7, 8);
            gp[p] = pack2(a, c);
        }
        const float g24 = __shfl_sync(0xffffffffu, hown[3], 0, 8);

        #pragma unroll
        for (int i = 0; i < 4; i++) {
            ull aA = pack2(fmaf(xcur.x, wx0[i], wb[i]),
                           fmaf(xcur.y, wx1[i], g24 * wh24[i]));
            ull aB = pack2(0.f, 0.f);
            #pragma unroll
            for (int p = 0; p < 6; p++) {
                aA = fma2(gp[p],     whp[i][p],     aA);
                aB = fma2(gp[p + 6], whp[i][p + 6], aB);
            }
            const float2 lh = unpack2(add2(aA, aB));
            hown[i] = tanh_approx(lh.x + lh.y);
        }
    }

    // h2o: per-thread partials over owned h units, then width-8 butterfly
    float p[8];
    #pragma unroll
    for (int c = 0; c < 8; c++) p[c] = 0.f;
    #pragma unroll
    for (int i = 0; i < 4; i++) {
        const bool v = (i < 3) || (o == 0);
        const int  j = v ? (o + 8 * i) : 0;
        const float hv = v ? hown[i] : 0.f;
        #pragma unroll
        for (int c = 0; c < 8; c++)
            p[c] = fmaf(hv, h2o_w[j * 8 + c], p[c]);
    }
    #pragma unroll
    for (int d = 1; d < 8; d <<= 1) {
        #pragma unroll
        for (int c = 0; c < 8; c++)
            p[c] += __shfl_xor_sync(0xffffffffu, p[c], d, 8);
    }

    if (o == 0) {
        const size_t Z0 = (size_t)NB * NT * 2;   // offset of z0 in output
        float zc[4];
        #pragma unroll
        for (int c = 0; c < 4; c++) {
            const float m  = p[c]     + h2o_b[c];
            const float lv = p[c + 4] + h2o_b[c + 4];
            const float z  = fmaf(eps[(size_t)b * 4 + c], __expf(0.5f * lv), m);
            zc[c] = z;
            out[Z0 + (size_t)b * 4 + c]                      = z;   // z0
            out[Z0 + (size_t)NB * 4 + (size_t)b * 4 + c]     = m;   // qz0_mean
            out[Z0 + (size_t)2 * NB * 4 + (size_t)b * 4 + c] = lv;  // qz0_logvar
        }
        *(float4*)&g_z[(size_t)b * NT * 4] = make_float4(zc[0], zc[1], zc[2], zc[3]);
    }
}

// ---------------------------------------------------------------------------
// Phase 2: RK4 ODE scan, QUAD layout, 128-thread blocks (all 4 SMSPs used).
// lane = (q = lane>>2 -> batch, o = lane&3 -> unit owner). Thread o owns
// units j = o + 4i, i=0..4. 8 batches/warp, 512 warps evenly over SMSPs.
// Width-4 shuffles gather u vectors; 2-stage packed butterfly for k.
// Layer 1 packed into f32x2 pairs.
// ---------------------------------------------------------------------------
__global__ void __launch_bounds__(128) ode_kernel(
    const float* __restrict__ ts,
    const float* __restrict__ f1_w, const float* __restrict__ f1_b,
    const float* __restrict__ f2_w, const float* __restrict__ f2_b,
    const float* __restrict__ f3_w, const float* __restrict__ f3_b)
{
    __shared__ float sdt[NT - 1];
    const int lane = threadIdx.x & 31;
    const int wrp  = threadIdx.x >> 5;
    const int o    = lane & 3;
    const int q    = lane >> 2;
    const int b    = blockIdx.x * 32 + wrp * 8 + q;

    // layer-1 weights packed by unit pairs (o,o+4) and (o+8,o+12); unit o+16 scalar
    ull   w1p[2][4], b1p[2];
    float w1s[4], b1s;
    {
        const int ja = o, jb = o + 4, jc = o + 8, jd = o + 12, je = o + 16;
        #pragma unroll
        for (int l = 0; l < 4; l++) {
            w1p[0][l] = pack2(f1_w[l * 20 + ja], f1_w[l * 20 + jb]);
            w1p[1][l] = pack2(f1_w[l * 20 + jc], f1_w[l * 20 + jd]);
            w1s[l]    = f1_w[l * 20 + je];
        }
        b1p[0] = pack2(f1_b[ja], f1_b[jb]);
        b1p[1] = pack2(f1_b[jc], f1_b[jd]);
        b1s    = f1_b[je];
    }
    float b2r[5];
    ull   w2p[5][10], w3a[5], w3b[5];
    #pragma unroll
    for (int i = 0; i < 5; i++) {
        const int j = o + 4 * i;
        b2r[i] = f2_b[j];
        #pragma unroll
        for (int p = 0; p < 10; p++)
            w2p[i][p] = pack2(f2_w[(2 * p) * 20 + j], f2_w[(2 * p + 1) * 20 + j]);
        w3a[i] = pack2(f3_w[j * 4 + 0], f3_w[j * 4 + 1]);
        w3b[i] = pack2(f3_w[j * 4 + 2], f3_w[j * 4 + 3]);
    }
    const ull fb01 = pack2(f3_b[0], f3_b[1]);
    const ull fb23 = pack2(f3_b[2], f3_b[3]);

    for (int i = threadIdx.x; i < NT - 1; i += 128) sdt[i] = ts[i + 1] - ts[i];

    const float4 zv = *(const float4*)&g_z[(size_t)b * NT * 4];
    ull z01 = pack2(zv.x, zv.y), z23 = pack2(zv.z, zv.w);
    __syncthreads();

    for (int step = 0; step < NT - 1; step++) {
        const float dt = sdt[step];
        ull za01 = z01, za23 = z23;
        ull zs01 = pack2(0.f, 0.f), zs23 = pack2(0.f, 0.f);

        #pragma unroll
        for (int s4 = 0; s4 < 4; s4++) {
            const float2 a01 = unpack2(za01), a23 = unpack2(za23);
            const ull zd0 = pack2(a01.x, a01.x), zd1 = pack2(a01.y, a01.y);
            const ull zd2 = pack2(a23.x, a23.x), zd3 = pack2(a23.y, a23.y);
            // layer 1: 4 -> 20, packed pairs + scalar tail
            ull acc0 = b1p[0], acc1 = b1p[1];
            acc0 = fma2(zd0, w1p[0][0], acc0);  acc1 = fma2(zd0, w1p[1][0], acc1);
            acc0 = fma2(zd1, w1p[0][1], acc0);  acc1 = fma2(zd1, w1p[1][1], acc1);
            acc0 = fma2(zd2, w1p[0][2], acc0);  acc1 = fma2(zd2, w1p[1][2], acc1);
            acc0 = fma2(zd3, w1p[0][3], acc0);  acc1 = fma2(zd3, w1p[1][3], acc1);
            float acc4 = b1s;
            acc4 = fmaf(a01.x, w1s[0], acc4);
            acc4 = fmaf(a01.y, w1s[1], acc4);
            acc4 = fmaf(a23.x, w1s[2], acc4);
            acc4 = fmaf(a23.y, w1s[3], acc4);
            const float2 l01 = unpack2(acc0), l23 = unpack2(acc1);
            float u1own[5];
            u1own[0] = eluf(l01.x);
            u1own[1] = eluf(l01.y);
            u1own[2] = eluf(l23.x);
            u1own[3] = eluf(l23.y);
            u1own[4] = eluf(acc4);
            // gather u1[20] via width-4 shuffles (serves all 8 batches at once)
            ull up[10];
            #pragma unroll
            for (int p = 0; p < 10; p++) {
                const int j0 = 2 * p, j1 = 2 * p + 1;
                float x0 = __shfl_sync(0xffffffffu, u1own[j0 >> 2], j0 & 3, 4);
                float x1 = __shfl_sync(0xffffffffu, u1own[j1 >> 2], j1 & 3, 4);
                up[p] = pack2(x0, x1);
            }
            // layer 2: 20 -> 20, split dual accumulators
            float u2own[5];
            #pragma unroll
            for (int i = 0; i < 5; i++) {
                ull aA = pack2(b2r[i], 0.f);
                ull aB = pack2(0.f, 0.f);
                #pragma unroll
                for (int p = 0; p < 5; p++) {
                    aA = fma2(up[p],     w2p[i][p],     aA);
                    aB = fma2(up[p + 5], w2p[i][p + 5], aB);
                }
                const float2 lh = unpack2(add2(aA, aB));
                u2own[i] = eluf(lh.x + lh.y);
            }
            // layer 3: 20 -> 4, packed partials + 2-stage width-4 butterfly
            ull k01 = pack2(0.f, 0.f), k23 = pack2(0.f, 0.f);
            #pragma unroll
            for (int i = 0; i < 5; i++) {
                const ull uu = pack2(u2own[i], u2own[i]);
                k01 = fma2(uu, w3a[i], k01);
                k23 = fma2(uu, w3b[i], k23);
            }
            k01 = add2(k01, shflx2(k01, 1, 4));
            k23 = add2(k23, shflx2(k23, 1, 4));
            k01 = add2(k01, shflx2(k01, 2, 4));
            k23 = add2(k23, shflx2(k23, 2, 4));
            k01 = add2(k01, fb01);
            k23 = add2(k23, fb23);

            const float wf = (s4 == 0 || s4 == 3) ? 1.0f : 2.0f;
            const ull ws = pack2(wf, wf);
            zs01 = fma2(ws, k01, zs01);
            zs23 = fma2(ws, k23, zs23);
            if (s4 < 3) {
                const float cc = (s4 == 2) ? dt : 0.5f * dt;
                const ull cp = pack2(cc, cc);
                za01 = fma2(cp, k01, z01);
                za23 = fma2(cp, k23, z23);
            }
        }

        const float dt6 = dt * (1.0f / 6.0f);
        const ull d6 = pack2(dt6, dt6);
        z01 = fma2(d6, zs01, z01);
        z23 = fma2(d6, zs23, z23);
        if (o == 0) {
            const float2 r01 = unpack2(z01), r23 = unpack2(z23);
            *(float4*)&g_z[((size_t)b * NT + step + 1) * 4] =
                make_float4(r01.x, r01.y, r23.x, r23.y);
        }
    }
}

// ---------------------------------------------------------------------------
// Phase 3: decoder, fully parallel over (B, T). Coalesced.
// ---------------------------------------------------------------------------
__global__ void __launch_bounds__(256) decode_kernel(
    const float* __restrict__ d1_w, const float* __restrict__ d1_b,
    const float* __restrict__ d2_w, const float* __restrict__ d2_b,
    float* __restrict__ out)
{
    __shared__ __align__(16) float s1[20][4];
    __shared__ float sb1[20];
    __shared__ float s2[20][2];
    __shared__ float sb2[2];
    const int tid = threadIdx.x;
    if (tid < 80) {
        int j = tid >> 2, l = tid & 3;
        s1[j][l] = d1_w[l * 20 + j];
    }
    if (tid < 20) sb1[tid] = d1_b[tid];
    if (tid < 40) s2[tid >> 1][tid & 1] = d2_w[tid];
    if (tid < 2)  sb2[tid] = d2_b[tid];
    __syncthreads();

    const size_t gid = (size_t)blockIdx.x * 256 + tid;
    const float4 zvec = *(const float4*)&g_z[gid * 4];
    float o0 = sb2[0], o1 = sb2[1];
    #pragma unroll
    for (int j = 0; j < 20; j++) {
        const float4 wv = *(const float4*)&s1[j][0];
        float a = sb1[j];
        a = fmaf(zvec.x, wv.x, a);
        a = fmaf(zvec.y, wv.y, a);
        a = fmaf(zvec.z, wv.z, a);
        a = fmaf(zvec.w, wv.w, a);
        a = fmaxf(a, 0.0f);
        o0 = fmaf(a, s2[j][0], o0);
        o1 = fmaf(a, s2[j][1], o1);
    }
    *(float2*)&out[gid * 2] = make_float2(o0, o1);
}

// ---------------------------------------------------------------------------
extern "C" void kernel_launch(void* const* d_in, const int* in_sizes, int n_in,
                              void* d_out, int out_size)
{
    const float* trajs = (const float*)d_in[0];
    const float* ts    = (const float*)d_in[1];
    const float* eps   = (const float*)d_in[2];
    const float* i2h_w = (const float*)d_in[3];
    const float* i2h_b = (const float*)d_in[4];
    const float* h2o_w = (const float*)d_in[5];
    const float* h2o_b = (const float*)d_in[6];
    const float* f1_w  = (const float*)d_in[7];
    const float* f1_b  = (const float*)d_in[8];
    const float* f2_w  = (const float*)d_in[9];
    const float* f2_b  = (const float*)d_in[10];
    const float* f3_w  = (const float*)d_in[11];
    const float* f3_b  = (const float*)d_in[12];
    const float* d1_w  = (const float*)d_in[13];
    const float* d1_b  = (const float*)d_in[14];
    const float* d2_w  = (const float*)d_in[15];
    const float* d2_b  = (const float*)d_in[16];
    float* out = (float*)d_out;

    rnn_kernel<<<NB / 16, 128>>>(trajs, eps, i2h_w, i2h_b, h2o_w, h2o_b, out);
    ode_kernel<<<NB / 32, 128>>>(ts, f1_w, f1_b, f2_w, f2_b, f3_w, f3_b);
    decode_kernel<<<(NB * NT) / 256, 256>>>(d1_w, d1_b, d2_w, d2_b, out);
}

// round 10
// speedup vs baseline: 1.6610x; 1.6610x over previous
#include <cuda_runtime.h>
#include <cstdint>
#include <cstddef>

#define NB 4096
#define NT 512

using ull = unsigned long long;

__device__ __forceinline__ ull pack2(float lo, float hi) {
    ull r; asm("mov.b64 %0, {%1, %2};" : "=l"(r) : "f"(lo), "f"(hi)); return r;
}
__device__ __forceinline__ float2 unpack2(ull v) {
    float2 r; asm("mov.b64 {%0, %1}, %2;" : "=f"(r.x), "=f"(r.y) : "l"(v)); return r;
}
// packed f32x2 FMA / ADD — PTX-only on sm_10x
__device__ __forceinline__ ull fma2(ull a, ull b, ull c) {
    ull d; asm("fma.rn.f32x2 %0, %1, %2, %3;" : "=l"(d) : "l"(a), "l"(b), "l"(c)); return d;
}
__device__ __forceinline__ ull add2(ull a, ull b) {
    ull d; asm("add.rn.f32x2 %0, %1, %2;" : "=l"(d) : "l"(a), "l"(b)); return d;
}
__device__ __forceinline__ ull shflx2(ull v, int d, int w) {
    float2 f = unpack2(v);
    f.x = __shfl_xor_sync(0xffffffffu, f.x, d, w);
    f.y = __shfl_xor_sync(0xffffffffu, f.y, d, w);
    return pack2(f.x, f.y);
}

// single-MUFU tanh (sm_75+), ~1e-4 accuracy, 16 cyc on the recurrent chain
__device__ __forceinline__ float tanh_approx(float x) {
    float r; asm("tanh.approx.f32 %0, %1;" : "=f"(r) : "f"(x)); return r;
}
__device__ __forceinline__ float eluf(float x) {
    return x > 0.0f ? x : (__expf(x) - 1.0f);
}

// ---------------------------------------------------------------------------
// Phase 1: reverse RNN scan + h2o + z0 (+mean/logvar).  Octet layout,
// 64-thread blocks, grid 512 (empirically fastest config, R7).
// lane = (s = lane>>3 -> batch, o = lane&7 -> unit group). Thread o owns
// hidden units {o, o+8, o+16} and (o==0) unit 24. State in registers,
// gathered per step with width-8 shuffles. No smem, no barriers.
// ---------------------------------------------------------------------------
__global__ void __launch_bounds__(64) rnn_kernel(
    const float* __restrict__ trajs,
    const float* __restrict__ eps,
    const float* __restrict__ i2h_w,
    const float* __restrict__ i2h_b,
    const float* __restrict__ h2o_w,
    const float* __restrict__ h2o_b,
    float* __restrict__ out)
{
    const int lane = threadIdx.x & 31;
    const int wrp  = threadIdx.x >> 5;
    const int o    = lane & 7;
    const int b    = blockIdx.x * 8 + wrp * 4 + (lane >> 3);

    // per-thread weight slots (zero-masked invalid slots -> uniform flow)
    float wx0[4], wx1[4], wb[4], wh24[4];
    ull   whp[4][12];
    #pragma unroll
    for (int i = 0; i < 4; i++) {
        const bool v = (i < 3) || (o == 0);
        const int  j = v ? (o + 8 * i) : 0;
        const float sc = v ? 1.0f : 0.0f;
        wx0[i] = sc * i2h_w[0 * 25 + j];
        wx1[i] = sc * i2h_w[1 * 25 + j];
        wb[i]  = sc * i2h_b[j];
        #pragma unroll
        for (int p = 0; p < 12; p++)
            whp[i][p] = pack2(sc * i2h_w[(2 + 2 * p) * 25 + j],
                              sc * i2h_w[(3 + 2 * p) * 25 + j]);
        wh24[i] = sc * i2h_w[26 * 25 + j];
    }

    float hown[4] = {0.f, 0.f, 0.f, 0.f};
    const float* tb = trajs + (size_t)b * (NT * 2);
    float2 xv = *(const float2*)(tb + (NT - 1) * 2);   // prefetch

    for (int t = NT - 1; t >= 0; t--) {
        const float2 xcur = xv;
        if (t > 0) xv = *(const float2*)(tb + (t - 1) * 2);  // overlap next load

        // gather full h[25] of this batch from octet registers
        ull gp[12];
        #pragma unroll
        for (int p = 0; p < 12; p++) {
            const int j0 = 2 * p, j1 = 2 * p + 1;
            float a = __shfl_sync(0xffffffffu, hown[j0 >> 3], j0 & 7, 8);
            float c = __shfl_sync(0xffffffffu, hown[j1 >> 3], j1 & 7, 8);
            gp[p] = pack2(a, c);
        }
        const float g24 = __shfl_sync(0xffffffffu, hown[3], 0, 8);

        #pragma unroll
        for (int i = 0; i < 4; i++) {
            ull aA = pack2(fmaf(xcur.x, wx0[i], wb[i]),
                           fmaf(xcur.y, wx1[i], g24 * wh24[i]));
            ull aB = pack2(0.f, 0.f);
            #pragma unroll
            for (int p = 0; p < 6; p++) {
                aA = fma2(gp[p],     whp[i][p],     aA);
                aB = fma2(gp[p + 6], whp[i][p + 6], aB);
            }
            const float2 lh = unpack2(add2(aA, aB));
            hown[i] = tanh_approx(lh.x + lh.y);
        }
    }

    // h2o: per-thread partials over owned h units, then width-8 butterfly
    float p[8];
    #pragma unroll
    for (int c = 0; c < 8; c++) p[c] = 0.f;
    #pragma unroll
    for (int i = 0; i < 4; i++) {
        const bool v = (i < 3) || (o == 0);
        const int  j = v ? (o + 8 * i) : 0;
        const float hv = v ? hown[i] : 0.f;
        #pragma unroll
        for (int c = 0; c < 8; c++)
            p[c] = fmaf(hv, h2o_w[j * 8 + c], p[c]);
    }
    #pragma unroll
    for (int d = 1; d < 8; d <<= 1) {
        #pragma unroll
        for (int c = 0; c < 8; c++)
            p[c] += __shfl_xor_sync(0xffffffffu, p[c], d, 8);
    }

    if (o == 0) {
        const size_t Z0 = (size_t)NB * NT * 2;   // offset of z0 in output
        #pragma unroll
        for (int c = 0; c < 4; c++) {
            const float m  = p[c]     + h2o_b[c];
            const float lv = p[c + 4] + h2o_b[c + 4];
            const float z  = fmaf(eps[(size_t)b * 4 + c], __expf(0.5f * lv), m);
            out[Z0 + (size_t)b * 4 + c]                      = z;   // z0
            out[Z0 + (size_t)NB * 4 + (size_t)b * 4 + c]     = m;   // qz0_mean
            out[Z0 + (size_t)2 * NB * 4 + (size_t)b * 4 + c] = lv;  // qz0_logvar
        }
    }
}

// ---------------------------------------------------------------------------
// Phase 2: RK4 ODE scan + FUSED decoder. QUAD layout, 64-thread blocks,
// grid 256 (R8 known-good config). lane = (q = lane>>2 -> batch, o = lane&3
// -> unit owner). Thread o owns units j = o + 4i, i=0..4. 8 batches/warp.
// Decoder (relu MLP 4->20->2) computed per step from the final z — its
// instructions are independent of the next step's chain and fill stall
// shadows. pred_x written directly; no z scratch in global memory at all.
// z0 is read from the out buffer (written by rnn_kernel).
// ---------------------------------------------------------------------------
__global__ void __launch_bounds__(64) ode_kernel(
    const float* __restrict__ ts,
    const float* __restrict__ f1_w, const float* __restrict__ f1_b,
    const float* __restrict__ f2_w, const float* __restrict__ f2_b,
    const float* __restrict__ f3_w, const float* __restrict__ f3_b,
    const float* __restrict__ d1_w, const float* __restrict__ d1_b,
    const float* __restrict__ d2_w, const float* __restrict__ d2_b,
    float* __restrict__ out)
{
    __shared__ float sdt[NT - 1];
    const int lane = threadIdx.x & 31;
    const int wrp  = threadIdx.x >> 5;
    const int o    = lane & 3;
    const int q    = lane >> 2;
    const int b    = blockIdx.x * 16 + wrp * 8 + q;

    float w1r[5][4], b1r[5], b2r[5];
    ull   w2p[5][10], w3a[5], w3b[5];
    #pragma unroll
    for (int i = 0; i < 5; i++) {
        const int j = o + 4 * i;
        #pragma unroll
        for (int l = 0; l < 4; l++) w1r[i][l] = f1_w[l * 20 + j];
        b1r[i] = f1_b[j];
        b2r[i] = f2_b[j];
        #pragma unroll
        for (int p = 0; p < 10; p++)
            w2p[i][p] = pack2(f2_w[(2 * p) * 20 + j], f2_w[(2 * p + 1) * 20 + j]);
        w3a[i] = pack2(f3_w[j * 4 + 0], f3_w[j * 4 + 1]);
        w3b[i] = pack2(f3_w[j * 4 + 2], f3_w[j * 4 + 3]);
    }
    const ull fb01 = pack2(f3_b[0], f3_b[1]);
    const ull fb23 = pack2(f3_b[2], f3_b[3]);

    // decoder weights for own 5 units
    float dc1[5][4], db1[5];
    ull   dc2[5];
    #pragma unroll
    for (int i = 0; i < 5; i++) {
        const int j = o + 4 * i;
        #pragma unroll
        for (int l = 0; l < 4; l++) dc1[i][l] = d1_w[l * 20 + j];
        db1[i] = d1_b[j];
        dc2[i] = pack2(d2_w[j * 2 + 0], d2_w[j * 2 + 1]);
    }
    const ull d2bp = pack2(d2_b[0], d2_b[1]);

    for (int i = threadIdx.x; i < NT - 1; i += 64) sdt[i] = ts[i + 1] - ts[i];

    const size_t Z0 = (size_t)NB * NT * 2;
    const float4 zv = *(const float4*)&out[Z0 + (size_t)b * 4];
    ull z01 = pack2(zv.x, zv.y), z23 = pack2(zv.z, zv.w);
    __syncthreads();

    // decode emit for (z01, z23) at time index t
    auto decode_emit = [&](ull dz01, ull dz23, int t) {
        const float2 c01 = unpack2(dz01), c23 = unpack2(dz23);
        ull acc = d2bp;
        #pragma unroll
        for (int i = 0; i < 5; i++) {
            float a = db1[i];
            a = fmaf(c01.x, dc1[i][0], a);
            a = fmaf(c01.y, dc1[i][1], a);
            a = fmaf(c23.x, dc1[i][2], a);
            a = fmaf(c23.y, dc1[i][3], a);
            a = fmaxf(a, 0.0f);
            acc = fma2(pack2(a, a), dc2[i], acc);
        }
        acc = add2(acc, shflx2(acc, 1, 4));
        acc = add2(acc, shflx2(acc, 2, 4));
        if (o == 0) {
            const float2 r = unpack2(acc);
            *(float2*)&out[((size_t)b * NT + t) * 2] = make_float2(r.x, r.y);
        }
    };

    decode_emit(z01, z23, 0);

    for (int step = 0; step < NT - 1; step++) {
        const float dt = sdt[step];
        ull za01 = z01, za23 = z23;
        ull zs01 = pack2(0.f, 0.f), zs23 = pack2(0.f, 0.f);

        #pragma unroll
        for (int s4 = 0; s4 < 4; s4++) {
            const float2 a01 = unpack2(za01), a23 = unpack2(za23);
            // layer 1: 4 -> 20 (own 5 units, ILP 5)
            float u1own[5];
            #pragma unroll
            for (int i = 0; i < 5; i++) {
                float a = b1r[i];
                a = fmaf(a01.x, w1r[i][0], a);
                a = fmaf(a01.y, w1r[i][1], a);
                a = fmaf(a23.x, w1r[i][2], a);
                a = fmaf(a23.y, w1r[i][3], a);
                u1own[i] = eluf(a);
            }
            // gather u1[20] via width-4 shuffles
            ull up[10];
            #pragma unroll
            for (int p = 0; p < 10; p++) {
                const int j0 = 2 * p, j1 = 2 * p + 1;
                float x0 = __shfl_sync(0xffffffffu, u1own[j0 >> 2], j0 & 3, 4);
                float x1 = __shfl_sync(0xffffffffu, u1own[j1 >> 2], j1 & 3, 4);
                up[p] = pack2(x0, x1);
            }
            // layer 2: 20 -> 20, split dual accumulators
            float u2own[5];
            #pragma unroll
            for (int i = 0; i < 5; i++) {
                ull aA = pack2(b2r[i], 0.f);
                ull aB = pack2(0.f, 0.f);
                #pragma unroll
                for (int p = 0; p < 5; p++) {
                    aA = fma2(up[p],     w2p[i][p],     aA);
                    aB = fma2(up[p + 5], w2p[i][p + 5], aB);
                }
                const float2 lh = unpack2(add2(aA, aB));
                u2own[i] = eluf(lh.x + lh.y);
            }
            // layer 3: 20 -> 4, packed partials + 2-stage width-4 butterfly
            ull k01 = pack2(0.f, 0.f), k23 = pack2(0.f, 0.f);
            #pragma unroll
            for (int i = 0; i < 5; i++) {
                const ull uu = pack2(u2own[i], u2own[i]);
                k01 = fma2(uu, w3a[i], k01);
                k23 = fma2(uu, w3b[i], k23);
            }
            k01 = add2(k01, shflx2(k01, 1, 4));
            k23 = add2(k23, shflx2(k23, 1, 4));
            k01 = add2(k01, shflx2(k01, 2, 4));
            k23 = add2(k23, shflx2(k23, 2, 4));
            k01 = add2(k01, fb01);
            k23 = add2(k23, fb23);

            const float wf = (s4 == 0 || s4 == 3) ? 1.0f : 2.0f;
            const ull ws = pack2(wf, wf);
            zs01 = fma2(ws, k01, zs01);
            zs23 = fma2(ws, k23, zs23);
            if (s4 < 3) {
                const float cc = (s4 == 2) ? dt : 0.5f * dt;
                const ull cp = pack2(cc, cc);
                za01 = fma2(cp, k01, z01);
                za23 = fma2(cp, k23, z23);
            }
        }

        const float dt6 = dt * (1.0f / 6.0f);
        const ull d6 = pack2(dt6, dt6);
        z01 = fma2(d6, zs01, z01);
        z23 = fma2(d6, zs23, z23);

        // fused decoder: independent of the next step's chain -> fills
        // stall shadows of the following iteration
        decode_emit(z01, z23, step + 1);
    }
}

// ---------------------------------------------------------------------------
extern "C" void kernel_launch(void* const* d_in, const int* in_sizes, int n_in,
                              void* d_out, int out_size)
{
    const float* trajs = (const float*)d_in[0];
    const float* ts    = (const float*)d_in[1];
    const float* eps   = (const float*)d_in[2];
    const float* i2h_w = (const float*)d_in[3];
    const float* i2h_b = (const float*)d_in[4];
    const float* h2o_w = (const float*)d_in[5];
    const float* h2o_b = (const float*)d_in[6];
    const float* f1_w  = (const float*)d_in[7];
    const float* f1_b  = (const float*)d_in[8];
    const float* f2_w  = (const float*)d_in[9];
    const float* f2_b  = (const float*)d_in[10];
    const float* f3_w  = (const float*)d_in[11];
    const float* f3_b  = (const float*)d_in[12];
    const float* d1_w  = (const float*)d_in[13];
    const float* d1_b  = (const float*)d_in[14];
    const float* d2_w  = (const float*)d_in[15];
    const float* d2_b  = (const float*)d_in[16];
    float* out = (float*)d_out;

    rnn_kernel<<<NB / 8, 64>>>(trajs, eps, i2h_w, i2h_b, h2o_w, h2o_b, out);
    ode_kernel<<<NB / 16, 64>>>(ts, f1_w, f1_b, f2_w, f2_b, f3_w, f3_b,
                                d1_w, d1_b, d2_w, d2_b, out);
}